// round 1
// baseline (speedup 1.0000x reference)
#include <cuda_runtime.h>
#include <math.h>

#define BATCH   4
#define SEQL    2048
#define DMODEL  1024
#define DINNER  2048
#define NST     16
#define LC      64
#define TCH     (SEQL / LC)   // 32 chunks

// ---------------- scratch (device globals; no allocation allowed) ----------
__device__ float g_buf0 [BATCH * SEQL * DINNER];   // x_pre (silu'd ssm half), later reused as y (pre out_proj)
__device__ float g_gate [BATCH * SEQL * DINNER];   // silu(x_res)
__device__ float g_xconv[BATCH * SEQL * DINNER];   // post-conv x_ssm
__device__ float g_B    [BATCH * SEQL * NST];
__device__ float g_C    [BATCH * SEQL * NST];
__device__ float g_hend [BATCH * TCH * DINNER * NST];
__device__ float g_Hst  [BATCH * TCH * DINNER * NST];

__device__ __forceinline__ float siluf(float v) { return v / (1.0f + expf(-v)); }

// ---------------- SGEMM: 128x128 tile, K-step 8, 256 threads, 8x8/thread ---
// MODE 0: A = param (x), out = g_buf0 / g_gate with silu-split epilogue
// MODE 1: A = g_buf0,    out = param with +bias epilogue
template <int MODE, int N, int K>
__launch_bounds__(256, 2)
__global__ void sgemm_kernel(const float* __restrict__ A,
                             const float* __restrict__ Bw,
                             const float* __restrict__ bias,
                             float* __restrict__ out)
{
    __shared__ float As[8][128];
    __shared__ float Bs[8][128];

    const float* Ap = (MODE == 0) ? A : g_buf0;

    const int tid = threadIdx.x;
    const int bn = blockIdx.x, bm = blockIdx.y;
    const int tx = tid & 15, ty = tid >> 4;

    const int arow = tid >> 1;          // 0..127
    const int acol = (tid & 1) * 4;     // 0 / 4
    const int brow = tid >> 5;          // 0..7
    const int bcol = (tid & 31) * 4;    // 0..124

    const float* Aptr = Ap + (size_t)(bm * 128 + arow) * K + acol;
    const float* Bptr = Bw + (size_t)brow * N + bn * 128 + bcol;

    float acc[8][8];
#pragma unroll
    for (int i = 0; i < 8; i++)
#pragma unroll
        for (int j = 0; j < 8; j++) acc[i][j] = 0.0f;

    for (int kt = 0; kt < K; kt += 8) {
        float4 av = *(const float4*)(Aptr + kt);
        float4 bv = *(const float4*)(Bptr + (size_t)kt * N);
        As[acol + 0][arow] = av.x;
        As[acol + 1][arow] = av.y;
        As[acol + 2][arow] = av.z;
        As[acol + 3][arow] = av.w;
        *(float4*)&Bs[brow][bcol] = bv;
        __syncthreads();

#pragma unroll
        for (int k = 0; k < 8; k++) {
            float ra[8], rb[8];
            *(float4*)&ra[0] = *(const float4*)&As[k][ty * 8];
            *(float4*)&ra[4] = *(const float4*)&As[k][ty * 8 + 4];
            *(float4*)&rb[0] = *(const float4*)&Bs[k][tx * 8];
            *(float4*)&rb[4] = *(const float4*)&Bs[k][tx * 8 + 4];
#pragma unroll
            for (int i = 0; i < 8; i++)
#pragma unroll
                for (int j = 0; j < 8; j++) acc[i][j] += ra[i] * rb[j];
        }
        __syncthreads();
    }

    const int gm = bm * 128 + ty * 8;
    const int gn = bn * 128 + tx * 8;

    float bb[8];
    *(float4*)&bb[0] = *(const float4*)(bias + gn);
    *(float4*)&bb[4] = *(const float4*)(bias + gn + 4);

    if (MODE == 0) {
        constexpr int HALF = N / 2;                 // 2048; 128 | 2048 so uniform per block
        const bool res = (gn >= HALF);
        float* dst = res ? g_gate : g_buf0;
        const int col = res ? (gn - HALF) : gn;
#pragma unroll
        for (int i = 0; i < 8; i++) {
            float v[8];
#pragma unroll
            for (int j = 0; j < 8; j++) v[j] = siluf(acc[i][j] + bb[j]);
            *(float4*)(dst + (size_t)(gm + i) * HALF + col)     = *(float4*)&v[0];
            *(float4*)(dst + (size_t)(gm + i) * HALF + col + 4) = *(float4*)&v[4];
        }
    } else {
#pragma unroll
        for (int i = 0; i < 8; i++) {
            float v[8];
#pragma unroll
            for (int j = 0; j < 8; j++) v[j] = acc[i][j] + bb[j];
            *(float4*)(out + (size_t)(gm + i) * N + gn)     = *(float4*)&v[0];
            *(float4*)(out + (size_t)(gm + i) * N + gn + 4) = *(float4*)&v[4];
        }
    }
}

// ---------------- depthwise conv(3) + B/C projections -----------------------
__global__ __launch_bounds__(256) void conv_bc_kernel(
    const float* __restrict__ conv_w, const float* __restrict__ conv_b,
    const float* __restrict__ W_B, const float* __restrict__ b_B,
    const float* __restrict__ B_mod,
    const float* __restrict__ W_C, const float* __restrict__ b_C,
    const float* __restrict__ C_mod)
{
    const int l = blockIdx.x;
    const int b = blockIdx.y;
    const int tid = threadIdx.x;

    const float* xrow = g_buf0 + (size_t)(b * SEQL + l) * DINNER;

    float pB[NST], pC[NST];
#pragma unroll
    for (int s = 0; s < NST; s++) { pB[s] = 0.0f; pC[s] = 0.0f; }

#pragma unroll
    for (int c = 0; c < DINNER / 256; c++) {
        const int d = tid + c * 256;
        const float w0 = conv_w[d * 3 + 0];
        const float w1 = conv_w[d * 3 + 1];
        const float w2 = conv_w[d * 3 + 2];
        float v = w1 * xrow[d] + conv_b[d];
        if (l > 0)        v += w0 * xrow[d - DINNER];
        if (l < SEQL - 1) v += w2 * xrow[d + DINNER];

        g_xconv[(size_t)(b * SEQL + l) * DINNER + d] = v;

        float4 wb[4], wc[4];
        const float4* wb4 = (const float4*)(W_B + (size_t)d * NST);
        const float4* wc4 = (const float4*)(W_C + (size_t)d * NST);
#pragma unroll
        for (int q = 0; q < 4; q++) { wb[q] = wb4[q]; wc[q] = wc4[q]; }
        const float* wbs = (const float*)wb;
        const float* wcs = (const float*)wc;
#pragma unroll
        for (int s = 0; s < NST; s++) {
            pB[s] += v * wbs[s];
            pC[s] += v * wcs[s];
        }
    }

    // warp butterfly reduce
#pragma unroll
    for (int s = 0; s < NST; s++) {
#pragma unroll
        for (int off = 16; off > 0; off >>= 1) {
            pB[s] += __shfl_xor_sync(0xffffffffu, pB[s], off);
            pC[s] += __shfl_xor_sync(0xffffffffu, pC[s], off);
        }
    }

    __shared__ float rB[8][NST], rC[8][NST];
    const int lane = tid & 31, warp = tid >> 5;
    if (lane == 0) {
#pragma unroll
        for (int s = 0; s < NST; s++) { rB[warp][s] = pB[s]; rC[warp][s] = pC[s]; }
    }
    __syncthreads();

    if (tid < NST) {
        float sB = 0.0f, sC = 0.0f;
#pragma unroll
        for (int w = 0; w < 8; w++) { sB += rB[w][tid]; sC += rC[w][tid]; }
        const size_t o = (size_t)(b * SEQL + l) * NST + tid;
        g_B[o] = sB + b_B[tid] + B_mod[b * NST + tid];
        g_C[o] = sC + b_C[tid] + C_mod[b * NST + tid];
    }
}

// ---------------- scan pass 1: per-chunk end state --------------------------
__global__ __launch_bounds__(256) void scan_pass1(const float* __restrict__ A_log)
{
    const int tid = threadIdx.x;
    const int d = blockIdx.x * 256 + tid;
    const int c = blockIdx.y;
    const int b = blockIdx.z;

    __shared__ float Bsh[LC * NST];
    {
        const float4* src = (const float4*)(g_B + (size_t)(b * SEQL + c * LC) * NST);
        ((float4*)Bsh)[tid] = src[tid];
    }

    float abar[NST];
#pragma unroll
    for (int s = 0; s < NST; s++)
        abar[s] = expf(-expf(A_log[d * NST + s]) * 0.1f);

    __syncthreads();

    float h[NST];
#pragma unroll
    for (int s = 0; s < NST; s++) h[s] = 0.0f;

    const float* xp = g_xconv + (size_t)(b * SEQL + c * LC) * DINNER + d;
#pragma unroll 4
    for (int k = 0; k < LC; k++) {
        const float x = xp[(size_t)k * DINNER];
#pragma unroll
        for (int s = 0; s < NST; s++) h[s] = abar[s] * h[s] + x * Bsh[k * NST + s];
    }

    float* hp = g_hend + ((((size_t)(b * TCH + c)) * DINNER + d) << 4);
#pragma unroll
    for (int q = 0; q < 4; q++) *(float4*)(hp + q * 4) = *(float4*)(h + q * 4);
}

// ---------------- scan pass 2: cross-chunk scan ------------------------------
__global__ __launch_bounds__(256) void scan_pass2(const float* __restrict__ A_log)
{
    const int gid = blockIdx.x * 256 + threadIdx.x;   // over BATCH*DINNER*NST
    const int s = gid & 15;
    const int d = (gid >> 4) & (DINNER - 1);
    const int b = gid >> 15;

    const float apow = expf(-expf(A_log[d * NST + s]) * 0.1f * (float)LC);

    float H = 0.0f;
    for (int c = 0; c < TCH; c++) {
        const size_t idx = ((((size_t)(b * TCH + c)) * DINNER + d) << 4) + s;
        g_Hst[idx] = H;
        H = apow * H + g_hend[idx];
    }
}

// ---------------- scan pass 3: full local scan + y + D*x + gate --------------
__global__ __launch_bounds__(256) void scan_pass3(const float* __restrict__ A_log,
                                                  const float* __restrict__ Dvec)
{
    const int tid = threadIdx.x;
    const int d = blockIdx.x * 256 + tid;
    const int c = blockIdx.y;
    const int b = blockIdx.z;

    __shared__ float Bsh[LC * NST];
    __shared__ float Csh[LC * NST];
    {
        const size_t base = (size_t)(b * SEQL + c * LC) * NST;
        ((float4*)Bsh)[tid] = ((const float4*)(g_B + base))[tid];
        ((float4*)Csh)[tid] = ((const float4*)(g_C + base))[tid];
    }

    float abar[NST];
#pragma unroll
    for (int s = 0; s < NST; s++)
        abar[s] = expf(-expf(A_log[d * NST + s]) * 0.1f);
    const float Dd = Dvec[d];

    float h[NST];
    {
        const float* Hp = g_Hst + ((((size_t)(b * TCH + c)) * DINNER + d) << 4);
#pragma unroll
        for (int q = 0; q < 4; q++) *(float4*)(h + q * 4) = *(const float4*)(Hp + q * 4);
    }

    __syncthreads();

    const size_t off = (size_t)(b * SEQL + c * LC) * DINNER + d;
    const float* xp = g_xconv + off;
    const float* gp = g_gate + off;
    float* yp = g_buf0 + off;     // reuse g_buf0 as y output

#pragma unroll 2
    for (int k = 0; k < LC; k++) {
        const float x = xp[(size_t)k * DINNER];
#pragma unroll
        for (int s = 0; s < NST; s++) h[s] = abar[s] * h[s] + x * Bsh[k * NST + s];
        float y0 = 0.0f, y1 = 0.0f;
#pragma unroll
        for (int s = 0; s < NST; s += 2) {
            y0 += h[s]     * Csh[k * NST + s];
            y1 += h[s + 1] * Csh[k * NST + s + 1];
        }
        float y = y0 + y1 + Dd * x;
        y *= gp[(size_t)k * DINNER];
        yp[(size_t)k * DINNER] = y;
    }
}

// ---------------- launch ------------------------------------------------------
extern "C" void kernel_launch(void* const* d_in, const int* in_sizes, int n_in,
                              void* d_out, int out_size)
{
    const float* x      = (const float*)d_in[0];
    const float* B_mod  = (const float*)d_in[1];
    const float* C_mod  = (const float*)d_in[2];
    const float* W_in   = (const float*)d_in[3];
    const float* b_in   = (const float*)d_in[4];
    const float* conv_w = (const float*)d_in[5];
    const float* conv_b = (const float*)d_in[6];
    const float* A_log  = (const float*)d_in[7];
    const float* Dv     = (const float*)d_in[8];
    const float* W_B    = (const float*)d_in[9];
    const float* b_B    = (const float*)d_in[10];
    const float* W_C    = (const float*)d_in[11];
    const float* b_C    = (const float*)d_in[12];
    const float* W_out  = (const float*)d_in[13];
    const float* b_out  = (const float*)d_in[14];
    float* out = (float*)d_out;

    // 1) in_proj + split + silu  : (8192 x 1024) @ (1024 x 4096)
    sgemm_kernel<0, 2 * DINNER, DMODEL><<<dim3(4096 / 128, (BATCH * SEQL) / 128), 256>>>(
        x, W_in, b_in, nullptr);

    // 2) depthwise conv + B/C projections
    conv_bc_kernel<<<dim3(SEQL, BATCH), 256>>>(conv_w, conv_b, W_B, b_B, B_mod, W_C, b_C, C_mod);

    // 3) chunked scan
    scan_pass1<<<dim3(DINNER / 256, TCH, BATCH), 256>>>(A_log);
    scan_pass2<<<(BATCH * DINNER * NST) / 256, 256>>>(A_log);
    scan_pass3<<<dim3(DINNER / 256, TCH, BATCH), 256>>>(A_log, Dv);

    // 4) out_proj : (8192 x 2048) @ (2048 x 1024)
    sgemm_kernel<1, DMODEL, DINNER><<<dim3(1024 / 128, (BATCH * SEQL) / 128), 256>>>(
        nullptr, W_out, b_out, out);
}

// round 4
// speedup vs baseline: 4.5602x; 4.5602x over previous
#include <cuda_runtime.h>
#include <cuda_fp16.h>
#include <math.h>
#include <stdint.h>

#define BATCH   4
#define SEQL    2048
#define DMODEL  1024
#define DINNER  2048
#define NST     16
#define LC      64
#define TCH     (SEQL / LC)     // 32
#define MTOT    (BATCH * SEQL)  // 8192

// ---------------- scratch (device globals) ----------------------------------
__device__ __align__(128) float  g_buf0 [MTOT * DINNER];   // silu'd ssm half (pre-conv)
__device__ __align__(128) float  g_gate [MTOT * DINNER];   // silu(x_res)
__device__ __align__(128) float  g_xconv[MTOT * DINNER];   // post-conv x_ssm
__device__ __align__(128) float  g_B    [MTOT * NST];
__device__ __align__(128) float  g_C    [MTOT * NST];
__device__ __align__(128) float  g_hend [BATCH * TCH * DINNER * NST];
__device__ __align__(128) float  g_Hst  [BATCH * TCH * DINNER * NST];
__device__ __align__(128) __half g_xa   [MTOT * DMODEL];    // x fp16        [M][K]
__device__ __align__(128) __half g_ya   [MTOT * DINNER];    // y fp16        [M][K]
__device__ __align__(128) __half g_wint [4096 * 1024];      // W_in^T fp16   [N][K]
__device__ __align__(128) __half g_wot  [1024 * 2048];      // W_out^T fp16  [N][K]

__device__ __forceinline__ float siluf(float v) { return v / (1.0f + expf(-v)); }

// ---------------- PTX helpers ------------------------------------------------
__device__ __forceinline__ uint32_t smem_u32(const void* p) {
    uint32_t a;
    asm("{ .reg .u64 t; cvta.to.shared.u64 t, %1; cvt.u32.u64 %0, t; }" : "=r"(a) : "l"(p));
    return a;
}
__device__ __forceinline__ void cp16(uint32_t dst, const void* src) {
    asm volatile("cp.async.cg.shared.global [%0], [%1], 16;" :: "r"(dst), "l"(src) : "memory");
}
__device__ __forceinline__ void cp_commit() {
    asm volatile("cp.async.commit_group;" ::: "memory");
}
__device__ __forceinline__ void ldsm_x4(uint32_t* r, uint32_t addr) {
    asm volatile("ldmatrix.sync.aligned.m8n8.x4.shared.b16 {%0,%1,%2,%3}, [%4];"
        : "=r"(r[0]), "=r"(r[1]), "=r"(r[2]), "=r"(r[3]) : "r"(addr));
}
__device__ __forceinline__ void ldsm_x2(uint32_t* r, uint32_t addr) {
    asm volatile("ldmatrix.sync.aligned.m8n8.x2.shared.b16 {%0,%1}, [%2];"
        : "=r"(r[0]), "=r"(r[1]) : "r"(addr));
}
__device__ __forceinline__ void mma16816(float* d, const uint32_t* a, const uint32_t* b) {
    asm volatile(
        "mma.sync.aligned.m16n8k16.row.col.f32.f16.f16.f32 "
        "{%0,%1,%2,%3}, {%4,%5,%6,%7}, {%8,%9}, {%0,%1,%2,%3};"
        : "+f"(d[0]), "+f"(d[1]), "+f"(d[2]), "+f"(d[3])
        : "r"(a[0]), "r"(a[1]), "r"(a[2]), "r"(a[3]), "r"(b[0]), "r"(b[1]));
}

// ---------------- HMMA fp16 GEMM ----------------------------------------------
// D[M,N] = A[M,K] @ B[N,K]^T ; A,B fp16 K-major ; fp32 accum in regs.
// Tile: BM=128, BN=128, BK=64 (128B/row, SW128 swizzle), 3-stage cp.async.
// 256 threads = 8 warps in 2(M) x 4(N); warp tile 64x32 = 4x4 m16n8k16.
#define NSTAGE 3
#define STAGEB 16384                      // one operand tile: 128 rows * 128 B
#define GSMEM  (NSTAGE * 2 * STAGEB)      // 96 KB

template<int K>
__device__ __forceinline__ void load_stage(uint32_t sb, const __half* Ag, const __half* Bg,
                                           int kt, int s, int r0, int c0) {
    const uint32_t abase = sb + s * (2 * STAGEB);
    const uint32_t bbase = abase + STAGEB;
    const __half* Ap = Ag + (size_t)kt * 64 + (size_t)r0 * K + c0 * 8;
    const __half* Bp = Bg + (size_t)kt * 64 + (size_t)r0 * K + c0 * 8;
    const uint32_t csw = (uint32_t)((c0 ^ (r0 & 7)) * 16);
#pragma unroll
    for (int p = 0; p < 4; p++) {
        const uint32_t off = (uint32_t)((r0 + p * 32) * 128) + csw;
        cp16(abase + off, Ap + (size_t)p * 32 * K);
        cp16(bbase + off, Bp + (size_t)p * 32 * K);
    }
}

template<int MODE, int N, int K>
__global__ void __launch_bounds__(256, 2) hgemm(const float* __restrict__ bias,
                                                float* __restrict__ out)
{
    extern __shared__ char smem[];
    const uint32_t sb = smem_u32(smem);
    const int tid = threadIdx.x, lane = tid & 31, wid = tid >> 5;
    const int bn = blockIdx.x, bm = blockIdx.y;

    const __half* Ag = (MODE == 0 ? g_xa : g_ya) + (size_t)bm * 128 * K;
    const __half* Bg = (MODE == 0 ? g_wint : g_wot) + (size_t)bn * 128 * K;
    const int r0 = tid >> 3, c0 = tid & 7;

#pragma unroll
    for (int s = 0; s < NSTAGE; s++) { load_stage<K>(sb, Ag, Bg, s, s, r0, c0); cp_commit(); }

    const int wm0 = (wid & 1) * 64;
    const int wn0 = (wid >> 1) * 32;

    float acc[4][4][4];
#pragma unroll
    for (int mt = 0; mt < 4; mt++)
#pragma unroll
        for (int nt = 0; nt < 4; nt++)
#pragma unroll
            for (int q = 0; q < 4; q++) acc[mt][nt][q] = 0.0f;

    const int ar = lane & 15;          // A ldmatrix row within 16
    const int ac = lane >> 4;          // A chunk sub-index (0/1)
    const int br = lane & 7;           // B ldmatrix row within 8
    const int bc = (lane >> 3) & 1;    // B chunk sub-index

    constexpr int KT = K / 64;
    int buf = 0;
    for (int kt = 0; kt < KT; kt++) {
        asm volatile("cp.async.wait_group %0;" :: "n"(NSTAGE - 1) : "memory");
        __syncthreads();
        const uint32_t abase = sb + buf * (2 * STAGEB);
        const uint32_t bbase = abase + STAGEB;
#pragma unroll
        for (int kk = 0; kk < 4; kk++) {
            uint32_t af[4][4], bf[4][2];
#pragma unroll
            for (int mt = 0; mt < 4; mt++) {
                const int row = wm0 + mt * 16 + ar;
                const int c = kk * 2 + ac;
                ldsm_x4(af[mt], abase + (uint32_t)(row * 128) + (uint32_t)((c ^ (row & 7)) << 4));
            }
#pragma unroll
            for (int nt = 0; nt < 4; nt++) {
                const int row = wn0 + nt * 8 + br;
                const int c = kk * 2 + bc;
                ldsm_x2(bf[nt], bbase + (uint32_t)(row * 128) + (uint32_t)((c ^ (row & 7)) << 4));
            }
#pragma unroll
            for (int mt = 0; mt < 4; mt++)
#pragma unroll
                for (int nt = 0; nt < 4; nt++)
                    mma16816(acc[mt][nt], af[mt], bf[nt]);
        }
        __syncthreads();
        const int next = kt + NSTAGE;
        if (next < KT) load_stage<K>(sb, Ag, Bg, next, buf, r0, c0);
        cp_commit();
        buf++; if (buf == NSTAGE) buf = 0;
    }

    // epilogue
    const int g = lane >> 2, t4 = lane & 3;
    if (MODE == 0) {
        constexpr int HALF = N / 2;   // 2048; 128 | 2048 -> uniform per CTA
        const int gn = bn * 128;
        float* dst = (gn < HALF) ? g_buf0 : g_gate;
        const int colb = (gn < HALF ? gn : gn - HALF) + wn0;
#pragma unroll
        for (int mt = 0; mt < 4; mt++) {
            const int gr = bm * 128 + wm0 + mt * 16 + g;
#pragma unroll
            for (int nt = 0; nt < 4; nt++) {
                const int col = colb + nt * 8 + t4 * 2;
                const float b0 = __ldg(bias + gn + wn0 + nt * 8 + t4 * 2);
                const float b1 = __ldg(bias + gn + wn0 + nt * 8 + t4 * 2 + 1);
                float2 v0 = make_float2(siluf(acc[mt][nt][0] + b0), siluf(acc[mt][nt][1] + b1));
                float2 v1 = make_float2(siluf(acc[mt][nt][2] + b0), siluf(acc[mt][nt][3] + b1));
                *(float2*)(dst + (size_t)gr * HALF + col)       = v0;
                *(float2*)(dst + (size_t)(gr + 8) * HALF + col) = v1;
            }
        }
    } else {
#pragma unroll
        for (int mt = 0; mt < 4; mt++) {
            const int gr = bm * 128 + wm0 + mt * 16 + g;
#pragma unroll
            for (int nt = 0; nt < 4; nt++) {
                const int col = bn * 128 + wn0 + nt * 8 + t4 * 2;
                const float b0 = __ldg(bias + col);
                const float b1 = __ldg(bias + col + 1);
                float2 v0 = make_float2(acc[mt][nt][0] + b0, acc[mt][nt][1] + b1);
                float2 v1 = make_float2(acc[mt][nt][2] + b0, acc[mt][nt][3] + b1);
                *(float2*)(out + (size_t)gr * N + col)       = v0;
                *(float2*)(out + (size_t)(gr + 8) * N + col) = v1;
            }
        }
    }
}

// ---------------- conversions -------------------------------------------------
__global__ __launch_bounds__(256) void convert_x(const float* __restrict__ x) {
    const int i = blockIdx.x * 256 + threadIdx.x;       // over MTOT*DMODEL/4
    const float4 v = ((const float4*)x)[i];
    __half2* o = (__half2*)g_xa;
    o[i * 2]     = __floats2half2_rn(v.x, v.y);
    o[i * 2 + 1] = __floats2half2_rn(v.z, v.w);
}

// WHICH=0 -> g_wint (K=1024, N=4096) ; WHICH=1 -> g_wot (K=2048, N=1024)
// NOTE: device globals must be referenced from DEVICE code, not passed from host.
template<int WHICH, int K, int N>
__global__ __launch_bounds__(256) void wtrans(const float* __restrict__ W) {
    __half* Wt = (WHICH == 0) ? g_wint : g_wot;
    __shared__ float t[32][33];
    const int bx = blockIdx.x * 32;   // n
    const int by = blockIdx.y * 32;   // k
    const int tx = threadIdx.x & 31;
    const int ty = threadIdx.x >> 5;  // 0..7
#pragma unroll
    for (int i = 0; i < 4; i++)
        t[ty + 8 * i][tx] = W[(size_t)(by + ty + 8 * i) * N + bx + tx];
    __syncthreads();
#pragma unroll
    for (int i = 0; i < 4; i++)
        Wt[(size_t)(bx + ty + 8 * i) * K + by + tx] = __float2half_rn(t[tx][ty + 8 * i]);
}

// ---------------- depthwise conv(3) -------------------------------------------
__global__ __launch_bounds__(256) void conv_kernel(const float* __restrict__ cw,
                                                   const float* __restrict__ cb) {
    const size_t i = (size_t)blockIdx.x * 256 + threadIdx.x;  // over MTOT*DINNER
    const int d = (int)(i & (DINNER - 1));
    const int l = (int)((i >> 11) & (SEQL - 1));
    float v = cw[d * 3 + 1] * g_buf0[i] + cb[d];
    if (l > 0)        v += cw[d * 3 + 0] * g_buf0[i - DINNER];
    if (l < SEQL - 1) v += cw[d * 3 + 2] * g_buf0[i + DINNER];
    g_xconv[i] = v;
}

// ---------------- B/C projection: init + ksplit GEMM --------------------------
__global__ __launch_bounds__(256) void bc_init(const float* __restrict__ b_B,
                                               const float* __restrict__ B_mod,
                                               const float* __restrict__ b_C,
                                               const float* __restrict__ C_mod) {
    const int i = blockIdx.x * 256 + threadIdx.x;   // over MTOT*NST
    const int s = i & 15;
    const int b = i >> 15;
    g_B[i] = b_B[s] + B_mod[b * 16 + s];
    g_C[i] = b_C[s] + C_mod[b * 16 + s];
}

__global__ __launch_bounds__(256) void bc_gemm(const float* __restrict__ W_B,
                                               const float* __restrict__ W_C) {
    __shared__ float As[32][65];
    __shared__ float Ws[32][32];
    const int tid = threadIdx.x;
    const int row0 = blockIdx.x * 64;
    const int kb0 = blockIdx.y * 512;
    const int j = tid & 31;
    const int mg = tid >> 5;

    float acc[8];
#pragma unroll
    for (int i = 0; i < 8; i++) acc[i] = 0.0f;

    for (int k0 = 0; k0 < 512; k0 += 32) {
#pragma unroll
        for (int p = 0; p < 8; p++) {
            const int mrow = mg + p * 8;
            As[j][mrow] = g_xconv[(size_t)(row0 + mrow) * DINNER + kb0 + k0 + j];
        }
        {
            const int kk = tid >> 3;
            const int jj = (tid & 7) * 4;
#pragma unroll
            for (int q = 0; q < 4; q++) {
                const int col = jj + q;
                Ws[kk][col] = (col < 16)
                    ? W_B[(size_t)(kb0 + k0 + kk) * 16 + col]
                    : W_C[(size_t)(kb0 + k0 + kk) * 16 + col - 16];
            }
        }
        __syncthreads();
#pragma unroll
        for (int k = 0; k < 32; k++) {
            const float w = Ws[k][j];
#pragma unroll
            for (int i = 0; i < 8; i++) acc[i] += As[k][mg * 8 + i] * w;
        }
        __syncthreads();
    }

#pragma unroll
    for (int i = 0; i < 8; i++) {
        const int row = row0 + mg * 8 + i;
        if (j < 16) atomicAdd(&g_B[(size_t)row * 16 + j], acc[i]);
        else        atomicAdd(&g_C[(size_t)row * 16 + j - 16], acc[i]);
    }
}

// ---------------- scan pass 1: per-chunk end state ----------------------------
__global__ __launch_bounds__(256) void scan_pass1(const float* __restrict__ A_log)
{
    const int tid = threadIdx.x;
    const int d = blockIdx.x * 256 + tid;
    const int c = blockIdx.y;
    const int b = blockIdx.z;

    __shared__ float Bsh[LC * NST];
    {
        const float4* src = (const float4*)(g_B + (size_t)(b * SEQL + c * LC) * NST);
        ((float4*)Bsh)[tid] = src[tid];
    }

    float abar[NST];
#pragma unroll
    for (int s = 0; s < NST; s++)
        abar[s] = expf(-expf(A_log[d * NST + s]) * 0.1f);

    __syncthreads();

    float h[NST];
#pragma unroll
    for (int s = 0; s < NST; s++) h[s] = 0.0f;

    const float* xp = g_xconv + (size_t)(b * SEQL + c * LC) * DINNER + d;
#pragma unroll 4
    for (int k = 0; k < LC; k++) {
        const float x = xp[(size_t)k * DINNER];
#pragma unroll
        for (int s = 0; s < NST; s++) h[s] = abar[s] * h[s] + x * Bsh[k * NST + s];
    }

    float* hp = g_hend + ((((size_t)(b * TCH + c)) * DINNER + d) << 4);
#pragma unroll
    for (int q = 0; q < 4; q++) *(float4*)(hp + q * 4) = *(float4*)(h + q * 4);
}

// ---------------- scan pass 2: cross-chunk scan -------------------------------
__global__ __launch_bounds__(256) void scan_pass2(const float* __restrict__ A_log)
{
    const int gid = blockIdx.x * 256 + threadIdx.x;
    const int s = gid & 15;
    const int d = (gid >> 4) & (DINNER - 1);
    const int b = gid >> 15;

    const float apow = expf(-expf(A_log[d * NST + s]) * 0.1f * (float)LC);

    float H = 0.0f;
    for (int c = 0; c < TCH; c++) {
        const size_t idx = ((((size_t)(b * TCH + c)) * DINNER + d) << 4) + s;
        g_Hst[idx] = H;
        H = apow * H + g_hend[idx];
    }
}

// ---------------- scan pass 3: local scan + y + D*x + gate -> fp16 ------------
__global__ __launch_bounds__(256) void scan_pass3(const float* __restrict__ A_log,
                                                  const float* __restrict__ Dvec)
{
    const int tid = threadIdx.x;
    const int d = blockIdx.x * 256 + tid;
    const int c = blockIdx.y;
    const int b = blockIdx.z;

    __shared__ float Bsh[LC * NST];
    __shared__ float Csh[LC * NST];
    {
        const size_t base = (size_t)(b * SEQL + c * LC) * NST;
        ((float4*)Bsh)[tid] = ((const float4*)(g_B + base))[tid];
        ((float4*)Csh)[tid] = ((const float4*)(g_C + base))[tid];
    }

    float abar[NST];
#pragma unroll
    for (int s = 0; s < NST; s++)
        abar[s] = expf(-expf(A_log[d * NST + s]) * 0.1f);
    const float Dd = Dvec[d];

    float h[NST];
    {
        const float* Hp = g_Hst + ((((size_t)(b * TCH + c)) * DINNER + d) << 4);
#pragma unroll
        for (int q = 0; q < 4; q++) *(float4*)(h + q * 4) = *(const float4*)(Hp + q * 4);
    }

    __syncthreads();

    const size_t off = (size_t)(b * SEQL + c * LC) * DINNER + d;
    const float* xp = g_xconv + off;
    const float* gp = g_gate + off;
    __half* yp = g_ya + off;

#pragma unroll 2
    for (int k = 0; k < LC; k++) {
        const float x = xp[(size_t)k * DINNER];
#pragma unroll
        for (int s = 0; s < NST; s++) h[s] = abar[s] * h[s] + x * Bsh[k * NST + s];
        float y0 = 0.0f, y1 = 0.0f;
#pragma unroll
        for (int s = 0; s < NST; s += 2) {
            y0 += h[s]     * Csh[k * NST + s];
            y1 += h[s + 1] * Csh[k * NST + s + 1];
        }
        float y = (y0 + y1 + Dd * x) * gp[(size_t)k * DINNER];
        yp[(size_t)k * DINNER] = __float2half_rn(y);
    }
}

// ---------------- launch --------------------------------------------------------
extern "C" void kernel_launch(void* const* d_in, const int* in_sizes, int n_in,
                              void* d_out, int out_size)
{
    const float* x      = (const float*)d_in[0];
    const float* B_mod  = (const float*)d_in[1];
    const float* C_mod  = (const float*)d_in[2];
    const float* W_in   = (const float*)d_in[3];
    const float* b_in   = (const float*)d_in[4];
    const float* conv_w = (const float*)d_in[5];
    const float* conv_b = (const float*)d_in[6];
    const float* A_log  = (const float*)d_in[7];
    const float* Dv     = (const float*)d_in[8];
    const float* W_B    = (const float*)d_in[9];
    const float* b_B    = (const float*)d_in[10];
    const float* W_C    = (const float*)d_in[11];
    const float* b_C    = (const float*)d_in[12];
    const float* W_out  = (const float*)d_in[13];
    const float* b_out  = (const float*)d_in[14];
    float* out = (float*)d_out;

    cudaFuncSetAttribute(hgemm<0, 4096, 1024>,
                         cudaFuncAttributeMaxDynamicSharedMemorySize, GSMEM);
    cudaFuncSetAttribute(hgemm<1, 1024, 2048>,
                         cudaFuncAttributeMaxDynamicSharedMemorySize, GSMEM);

    // fp16 conversions / weight transposes
    convert_x<<<(MTOT * DMODEL / 4) / 256, 256>>>(x);
    wtrans<0, 1024, 4096><<<dim3(4096 / 32, 1024 / 32), 256>>>(W_in);
    wtrans<1, 2048, 1024><<<dim3(1024 / 32, 2048 / 32), 256>>>(W_out);

    // 1) in_proj (HMMA fp16) + split + silu
    hgemm<0, 4096, 1024><<<dim3(4096 / 128, MTOT / 128), 256, GSMEM>>>(b_in, nullptr);

    // 2) depthwise conv, then B/C projections
    conv_kernel<<<(MTOT * DINNER) / 256, 256>>>(conv_w, conv_b);
    bc_init<<<(MTOT * NST) / 256, 256>>>(b_B, B_mod, b_C, C_mod);
    bc_gemm<<<dim3(MTOT / 64, 4), 256>>>(W_B, W_C);

    // 3) chunked scan
    scan_pass1<<<dim3(DINNER / 256, TCH, BATCH), 256>>>(A_log);
    scan_pass2<<<(BATCH * DINNER * NST) / 256, 256>>>(A_log);
    scan_pass3<<<dim3(DINNER / 256, TCH, BATCH), 256>>>(A_log, Dv);

    // 4) out_proj (HMMA fp16)
    hgemm<1, 1024, 2048><<<dim3(1024 / 128, MTOT / 128), 256, GSMEM>>>(b_out, out);
}

// round 5
// speedup vs baseline: 5.0028x; 1.0971x over previous
#include <cuda_runtime.h>
#include <cuda_fp16.h>
#include <math.h>
#include <stdint.h>

#define BATCH   4
#define SEQL    2048
#define DMODEL  1024
#define DINNER  2048
#define NST     16
#define LC      64
#define TCH     (SEQL / LC)     // 32
#define MTOT    (BATCH * SEQL)  // 8192

// ---------------- scratch (device globals) ----------------------------------
__device__ __align__(128) float  g_buf0 [MTOT * DINNER];   // silu'd ssm half (pre-conv)
__device__ __align__(128) float  g_gate [MTOT * DINNER];   // silu(x_res)
__device__ __align__(128) float  g_B    [MTOT * NST];
__device__ __align__(128) float  g_C    [MTOT * NST];
__device__ __align__(128) float  g_hend [BATCH * TCH * DINNER * NST];
__device__ __align__(128) float  g_Hst  [BATCH * TCH * DINNER * NST];
__device__ __align__(128) __half g_xa   [MTOT * DMODEL];    // x fp16        [M][K]
__device__ __align__(128) __half g_ya   [MTOT * DINNER];    // y fp16        [M][K]
__device__ __align__(128) __half g_wint [4096 * 1024];      // W_in^T fp16   [N][K]
__device__ __align__(128) __half g_wot  [1024 * 2048];      // W_out^T fp16  [N][K]

__device__ __forceinline__ float siluf(float v) { return v / (1.0f + expf(-v)); }

// ---------------- PTX helpers ------------------------------------------------
__device__ __forceinline__ uint32_t smem_u32(const void* p) {
    uint32_t a;
    asm("{ .reg .u64 t; cvta.to.shared.u64 t, %1; cvt.u32.u64 %0, t; }" : "=r"(a) : "l"(p));
    return a;
}
__device__ __forceinline__ void cp16(uint32_t dst, const void* src) {
    asm volatile("cp.async.cg.shared.global [%0], [%1], 16;" :: "r"(dst), "l"(src) : "memory");
}
__device__ __forceinline__ void cp_commit() {
    asm volatile("cp.async.commit_group;" ::: "memory");
}
__device__ __forceinline__ void ldsm_x4(uint32_t* r, uint32_t addr) {
    asm volatile("ldmatrix.sync.aligned.m8n8.x4.shared.b16 {%0,%1,%2,%3}, [%4];"
        : "=r"(r[0]), "=r"(r[1]), "=r"(r[2]), "=r"(r[3]) : "r"(addr));
}
__device__ __forceinline__ void ldsm_x2(uint32_t* r, uint32_t addr) {
    asm volatile("ldmatrix.sync.aligned.m8n8.x2.shared.b16 {%0,%1}, [%2];"
        : "=r"(r[0]), "=r"(r[1]) : "r"(addr));
}
__device__ __forceinline__ void mma16816(float* d, const uint32_t* a, const uint32_t* b) {
    asm volatile(
        "mma.sync.aligned.m16n8k16.row.col.f32.f16.f16.f32 "
        "{%0,%1,%2,%3}, {%4,%5,%6,%7}, {%8,%9}, {%0,%1,%2,%3};"
        : "+f"(d[0]), "+f"(d[1]), "+f"(d[2]), "+f"(d[3])
        : "r"(a[0]), "r"(a[1]), "r"(a[2]), "r"(a[3]), "r"(b[0]), "r"(b[1]));
}

// ---------------- HMMA fp16 GEMM ----------------------------------------------
// D[M,N] = A[M,K] @ B[N,K]^T ; fp32 accum in regs.
// BM=128, BN=128, BK=64 (SW128 swizzle), 3-stage cp.async, single-sync mainloop.
// 256 threads = 8 warps in 2(M) x 4(N); warp tile 64x32 = 4x4 m16n8k16.
#define NSTAGE 3
#define STAGEB 16384
#define GSMEM  (NSTAGE * 2 * STAGEB)      // 96 KB

template<int K>
__device__ __forceinline__ void load_stage(uint32_t sb, const __half* Ag, const __half* Bg,
                                           int kt, int s, int r0, int c0) {
    const uint32_t abase = sb + s * (2 * STAGEB);
    const uint32_t bbase = abase + STAGEB;
    const __half* Ap = Ag + (size_t)kt * 64 + (size_t)r0 * K + c0 * 8;
    const __half* Bp = Bg + (size_t)kt * 64 + (size_t)r0 * K + c0 * 8;
    const uint32_t csw = (uint32_t)((c0 ^ (r0 & 7)) * 16);
#pragma unroll
    for (int p = 0; p < 4; p++) {
        const uint32_t off = (uint32_t)((r0 + p * 32) * 128) + csw;
        cp16(abase + off, Ap + (size_t)p * 32 * K);
        cp16(bbase + off, Bp + (size_t)p * 32 * K);
    }
}

template<int MODE, int N, int K>
__global__ void __launch_bounds__(256, 2) hgemm(const float* __restrict__ bias,
                                                float* __restrict__ out)
{
    extern __shared__ char smem[];
    const uint32_t sb = smem_u32(smem);
    const int tid = threadIdx.x, lane = tid & 31, wid = tid >> 5;
    const int bn = blockIdx.x, bm = blockIdx.y;

    const __half* Ag = (MODE == 0 ? g_xa : g_ya) + (size_t)bm * 128 * K;
    const __half* Bg = (MODE == 0 ? g_wint : g_wot) + (size_t)bn * 128 * K;
    const int r0 = tid >> 3, c0 = tid & 7;

    // prologue: fill NSTAGE-1 stages
#pragma unroll
    for (int s = 0; s < NSTAGE - 1; s++) { load_stage<K>(sb, Ag, Bg, s, s, r0, c0); cp_commit(); }

    const int wm0 = (wid & 1) * 64;
    const int wn0 = (wid >> 1) * 32;

    float acc[4][4][4];
#pragma unroll
    for (int mt = 0; mt < 4; mt++)
#pragma unroll
        for (int nt = 0; nt < 4; nt++)
#pragma unroll
            for (int q = 0; q < 4; q++) acc[mt][nt][q] = 0.0f;

    const int ar = lane & 15;
    const int ac = lane >> 4;
    const int br = lane & 7;
    const int bc = (lane >> 3) & 1;

    constexpr int KT = K / 64;
    int buf = 0;                      // stage holding k-tile kt
    int wbuf = NSTAGE - 1;            // stage to fill next
    for (int kt = 0; kt < KT; kt++) {
        asm volatile("cp.async.wait_group %0;" :: "n"(NSTAGE - 2) : "memory");
        __syncthreads();

        // issue next load FIRST (into the stage consumed at kt-1), overlap with MMA
        const int next = kt + NSTAGE - 1;
        if (next < KT) load_stage<K>(sb, Ag, Bg, next, wbuf, r0, c0);
        cp_commit();
        wbuf++; if (wbuf == NSTAGE) wbuf = 0;

        const uint32_t abase = sb + buf * (2 * STAGEB);
        const uint32_t bbase = abase + STAGEB;
#pragma unroll
        for (int kk = 0; kk < 4; kk++) {
            uint32_t af[4][4], bf[4][2];
#pragma unroll
            for (int mt = 0; mt < 4; mt++) {
                const int row = wm0 + mt * 16 + ar;
                const int c = kk * 2 + ac;
                ldsm_x4(af[mt], abase + (uint32_t)(row * 128) + (uint32_t)((c ^ (row & 7)) << 4));
            }
#pragma unroll
            for (int nt = 0; nt < 4; nt++) {
                const int row = wn0 + nt * 8 + br;
                const int c = kk * 2 + bc;
                ldsm_x2(bf[nt], bbase + (uint32_t)(row * 128) + (uint32_t)((c ^ (row & 7)) << 4));
            }
#pragma unroll
            for (int mt = 0; mt < 4; mt++)
#pragma unroll
                for (int nt = 0; nt < 4; nt++)
                    mma16816(acc[mt][nt], af[mt], bf[nt]);
        }
        buf++; if (buf == NSTAGE) buf = 0;
    }

    // epilogue
    const int g = lane >> 2, t4 = lane & 3;
    if (MODE == 0) {
        constexpr int HALF = N / 2;
        const int gn = bn * 128;
        float* dst = (gn < HALF) ? g_buf0 : g_gate;
        const int colb = (gn < HALF ? gn : gn - HALF) + wn0;
#pragma unroll
        for (int mt = 0; mt < 4; mt++) {
            const int gr = bm * 128 + wm0 + mt * 16 + g;
#pragma unroll
            for (int nt = 0; nt < 4; nt++) {
                const int col = colb + nt * 8 + t4 * 2;
                const float b0 = __ldg(bias + gn + wn0 + nt * 8 + t4 * 2);
                const float b1 = __ldg(bias + gn + wn0 + nt * 8 + t4 * 2 + 1);
                float2 v0 = make_float2(siluf(acc[mt][nt][0] + b0), siluf(acc[mt][nt][1] + b1));
                float2 v1 = make_float2(siluf(acc[mt][nt][2] + b0), siluf(acc[mt][nt][3] + b1));
                *(float2*)(dst + (size_t)gr * HALF + col)       = v0;
                *(float2*)(dst + (size_t)(gr + 8) * HALF + col) = v1;
            }
        }
    } else {
#pragma unroll
        for (int mt = 0; mt < 4; mt++) {
            const int gr = bm * 128 + wm0 + mt * 16 + g;
#pragma unroll
            for (int nt = 0; nt < 4; nt++) {
                const int col = bn * 128 + wn0 + nt * 8 + t4 * 2;
                const float b0 = __ldg(bias + col);
                const float b1 = __ldg(bias + col + 1);
                float2 v0 = make_float2(acc[mt][nt][0] + b0, acc[mt][nt][1] + b1);
                float2 v1 = make_float2(acc[mt][nt][2] + b0, acc[mt][nt][3] + b1);
                *(float2*)(out + (size_t)gr * N + col)       = v0;
                *(float2*)(out + (size_t)(gr + 8) * N + col) = v1;
            }
        }
    }
}

// ---------------- fused prep: convert x + transpose both weights --------------
// blocks [0, 8192)                : x fp32 -> fp16
// blocks [8192, 8192+4096)        : W_in  (K=1024,N=4096) -> g_wint [N][K]
// blocks [8192+4096, +2048)       : W_out (K=2048,N=1024) -> g_wot  [N][K]
template<int K, int N>
__device__ __forceinline__ void wtrans_tile(const float* __restrict__ W, __half* Wt,
                                            int bx, int by, int tid) {
    __shared__ float t[32][33];
    const int tx = tid & 31;
    const int ty = tid >> 5;
#pragma unroll
    for (int i = 0; i < 4; i++)
        t[ty + 8 * i][tx] = W[(size_t)(by * 32 + ty + 8 * i) * N + bx * 32 + tx];
    __syncthreads();
#pragma unroll
    for (int i = 0; i < 4; i++)
        Wt[(size_t)(bx * 32 + ty + 8 * i) * K + by * 32 + tx] = __float2half_rn(t[tx][ty + 8 * i]);
}

__global__ __launch_bounds__(256) void prep(const float* __restrict__ x,
                                            const float* __restrict__ W_in,
                                            const float* __restrict__ W_out) {
    const int bid = blockIdx.x;
    if (bid < 8192) {
        const int i = bid * 256 + threadIdx.x;
        const float4 v = ((const float4*)x)[i];
        __half2* o = (__half2*)g_xa;
        o[i * 2]     = __floats2half2_rn(v.x, v.y);
        o[i * 2 + 1] = __floats2half2_rn(v.z, v.w);
    } else if (bid < 8192 + 4096) {
        const int idx = bid - 8192;                 // 128 n-blocks x 32 k-blocks
        wtrans_tile<1024, 4096>(W_in, g_wint, idx & 127, idx >> 7, threadIdx.x);
    } else {
        const int idx = bid - 8192 - 4096;          // 32 n-blocks x 64 k-blocks
        wtrans_tile<2048, 1024>(W_out, g_wot, idx & 31, idx >> 5, threadIdx.x);
    }
}

// ---------------- B/C projection (conv fused): init + ksplit GEMM -------------
__global__ __launch_bounds__(256) void bc_init(const float* __restrict__ b_B,
                                               const float* __restrict__ B_mod,
                                               const float* __restrict__ b_C,
                                               const float* __restrict__ C_mod) {
    const int i = blockIdx.x * 256 + threadIdx.x;
    const int s = i & 15;
    const int b = i >> 15;
    g_B[i] = b_B[s] + B_mod[b * 16 + s];
    g_C[i] = b_C[s] + C_mod[b * 16 + s];
}

__global__ __launch_bounds__(256) void bc_gemm(const float* __restrict__ W_B,
                                               const float* __restrict__ W_C,
                                               const float* __restrict__ cw,
                                               const float* __restrict__ cb) {
    __shared__ float As[32][65];
    __shared__ float Ws[32][32];
    const int tid = threadIdx.x;
    const int row0 = blockIdx.x * 64;
    const int kb0 = blockIdx.y * 512;
    const int j = tid & 31;
    const int mg = tid >> 5;

    float acc[8];
#pragma unroll
    for (int i = 0; i < 8; i++) acc[i] = 0.0f;

    for (int k0 = 0; k0 < 512; k0 += 32) {
        {
            const int d = kb0 + k0 + j;
            const float w0 = cw[d * 3 + 0], w1 = cw[d * 3 + 1], w2 = cw[d * 3 + 2];
            const float cbd = cb[d];
#pragma unroll
            for (int p = 0; p < 8; p++) {
                const int grow = row0 + mg + p * 8;
                const int l = grow & (SEQL - 1);
                const float* xc = g_buf0 + (size_t)grow * DINNER + d;
                float v = w1 * xc[0] + cbd;
                if (l > 0)        v += w0 * xc[-DINNER];
                if (l < SEQL - 1) v += w2 * xc[DINNER];
                As[j][mg + p * 8] = v;
            }
        }
        {
            const int kk = tid >> 3;
            const int jj = (tid & 7) * 4;
#pragma unroll
            for (int q = 0; q < 4; q++) {
                const int col = jj + q;
                Ws[kk][col] = (col < 16)
                    ? W_B[(size_t)(kb0 + k0 + kk) * 16 + col]
                    : W_C[(size_t)(kb0 + k0 + kk) * 16 + col - 16];
            }
        }
        __syncthreads();
#pragma unroll
        for (int k = 0; k < 32; k++) {
            const float w = Ws[k][j];
#pragma unroll
            for (int i = 0; i < 8; i++) acc[i] += As[k][mg * 8 + i] * w;
        }
        __syncthreads();
    }

#pragma unroll
    for (int i = 0; i < 8; i++) {
        const int row = row0 + mg * 8 + i;
        if (j < 16) atomicAdd(&g_B[(size_t)row * 16 + j], acc[i]);
        else        atomicAdd(&g_C[(size_t)row * 16 + j - 16], acc[i]);
    }
}

// ---------------- conv on the fly (rolling registers) --------------------------
struct ConvRoll {
    float w0, w1, w2, cbd;
    float xm, xc;
    const float* base;   // &g_buf0[row(l0)*DINNER + d]
    int l;
    __device__ __forceinline__ void init(const float* cw, const float* cb, int d,
                                         int b, int l0) {
        w0 = cw[d * 3 + 0]; w1 = cw[d * 3 + 1]; w2 = cw[d * 3 + 2]; cbd = cb[d];
        base = g_buf0 + (size_t)(b * SEQL + l0) * DINNER + d;
        l = l0;
        xc = base[0];
        xm = (l0 > 0) ? base[-DINNER] : 0.0f;
    }
    __device__ __forceinline__ float next() {   // conv value at current l, then advance
        const float xp = (l < SEQL - 1) ? base[DINNER] : 0.0f;
        const float v = w1 * xc + w0 * xm + w2 * xp + cbd;
        xm = xc; xc = xp; base += DINNER; l++;
        return v;
    }
};

// ---------------- scan pass 1: per-chunk end state (conv fused) ----------------
__global__ __launch_bounds__(256) void scan_pass1(const float* __restrict__ A_log,
                                                  const float* __restrict__ cw,
                                                  const float* __restrict__ cb)
{
    const int tid = threadIdx.x;
    const int d = blockIdx.x * 256 + tid;
    const int c = blockIdx.y;
    const int b = blockIdx.z;

    __shared__ float Bsh[LC * NST];
    {
        const float4* src = (const float4*)(g_B + (size_t)(b * SEQL + c * LC) * NST);
        ((float4*)Bsh)[tid] = src[tid];
    }

    float abar[NST];
#pragma unroll
    for (int s = 0; s < NST; s++)
        abar[s] = expf(-expf(A_log[d * NST + s]) * 0.1f);

    ConvRoll cr; cr.init(cw, cb, d, b, c * LC);
    __syncthreads();

    float h[NST];
#pragma unroll
    for (int s = 0; s < NST; s++) h[s] = 0.0f;

#pragma unroll 4
    for (int k = 0; k < LC; k++) {
        const float x = cr.next();
#pragma unroll
        for (int s = 0; s < NST; s++) h[s] = abar[s] * h[s] + x * Bsh[k * NST + s];
    }

    float* hp = g_hend + ((((size_t)(b * TCH + c)) * DINNER + d) << 4);
#pragma unroll
    for (int q = 0; q < 4; q++) *(float4*)(hp + q * 4) = *(float4*)(h + q * 4);
}

// ---------------- scan pass 2: cross-chunk scan --------------------------------
__global__ __launch_bounds__(256) void scan_pass2(const float* __restrict__ A_log)
{
    const int gid = blockIdx.x * 256 + threadIdx.x;
    const int s = gid & 15;
    const int d = (gid >> 4) & (DINNER - 1);
    const int b = gid >> 15;

    const float apow = expf(-expf(A_log[d * NST + s]) * 0.1f * (float)LC);

    float H = 0.0f;
    for (int c = 0; c < TCH; c++) {
        const size_t idx = ((((size_t)(b * TCH + c)) * DINNER + d) << 4) + s;
        g_Hst[idx] = H;
        H = apow * H + g_hend[idx];
    }
}

// ---------------- scan pass 3: local scan + y + D*x + gate (conv fused) --------
__global__ __launch_bounds__(256) void scan_pass3(const float* __restrict__ A_log,
                                                  const float* __restrict__ Dvec,
                                                  const float* __restrict__ cw,
                                                  const float* __restrict__ cb)
{
    const int tid = threadIdx.x;
    const int d = blockIdx.x * 256 + tid;
    const int c = blockIdx.y;
    const int b = blockIdx.z;

    __shared__ float Bsh[LC * NST];
    __shared__ float Csh[LC * NST];
    {
        const size_t base = (size_t)(b * SEQL + c * LC) * NST;
        ((float4*)Bsh)[tid] = ((const float4*)(g_B + base))[tid];
        ((float4*)Csh)[tid] = ((const float4*)(g_C + base))[tid];
    }

    float abar[NST];
#pragma unroll
    for (int s = 0; s < NST; s++)
        abar[s] = expf(-expf(A_log[d * NST + s]) * 0.1f);
    const float Dd = Dvec[d];

    float h[NST];
    {
        const float* Hp = g_Hst + ((((size_t)(b * TCH + c)) * DINNER + d) << 4);
#pragma unroll
        for (int q = 0; q < 4; q++) *(float4*)(h + q * 4) = *(const float4*)(Hp + q * 4);
    }

    ConvRoll cr; cr.init(cw, cb, d, b, c * LC);
    __syncthreads();

    const size_t off = (size_t)(b * SEQL + c * LC) * DINNER + d;
    const float* gp = g_gate + off;
    __half* yp = g_ya + off;

#pragma unroll 2
    for (int k = 0; k < LC; k++) {
        const float x = cr.next();
#pragma unroll
        for (int s = 0; s < NST; s++) h[s] = abar[s] * h[s] + x * Bsh[k * NST + s];
        float y0 = 0.0f, y1 = 0.0f;
#pragma unroll
        for (int s = 0; s < NST; s += 2) {
            y0 += h[s]     * Csh[k * NST + s];
            y1 += h[s + 1] * Csh[k * NST + s + 1];
        }
        float y = (y0 + y1 + Dd * x) * gp[(size_t)k * DINNER];
        yp[(size_t)k * DINNER] = __float2half_rn(y);
    }
}

// ---------------- launch ---------------------------------------------------------
extern "C" void kernel_launch(void* const* d_in, const int* in_sizes, int n_in,
                              void* d_out, int out_size)
{
    const float* x      = (const float*)d_in[0];
    const float* B_mod  = (const float*)d_in[1];
    const float* C_mod  = (const float*)d_in[2];
    const float* W_in   = (const float*)d_in[3];
    const float* b_in   = (const float*)d_in[4];
    const float* conv_w = (const float*)d_in[5];
    const float* conv_b = (const float*)d_in[6];
    const float* A_log  = (const float*)d_in[7];
    const float* Dv     = (const float*)d_in[8];
    const float* W_B    = (const float*)d_in[9];
    const float* b_B    = (const float*)d_in[10];
    const float* W_C    = (const float*)d_in[11];
    const float* b_C    = (const float*)d_in[12];
    const float* W_out  = (const float*)d_in[13];
    const float* b_out  = (const float*)d_in[14];
    float* out = (float*)d_out;

    cudaFuncSetAttribute(hgemm<0, 4096, 1024>,
                         cudaFuncAttributeMaxDynamicSharedMemorySize, GSMEM);
    cudaFuncSetAttribute(hgemm<1, 1024, 2048>,
                         cudaFuncAttributeMaxDynamicSharedMemorySize, GSMEM);

    // 0) fp16 conversions + weight transposes (fused)
    prep<<<8192 + 4096 + 2048, 256>>>(x, W_in, W_out);

    // 1) in_proj (HMMA fp16) + split + silu
    hgemm<0, 4096, 1024><<<dim3(4096 / 128, MTOT / 128), 256, GSMEM>>>(b_in, nullptr);

    // 2) B/C projections (conv fused into A-tile load)
    bc_init<<<(MTOT * NST) / 256, 256>>>(b_B, B_mod, b_C, C_mod);
    bc_gemm<<<dim3(MTOT / 64, 4), 256>>>(W_B, W_C, conv_w, conv_b);

    // 3) chunked scan (conv fused)
    scan_pass1<<<dim3(DINNER / 256, TCH, BATCH), 256>>>(A_log, conv_w, conv_b);
    scan_pass2<<<(BATCH * DINNER * NST) / 256, 256>>>(A_log);
    scan_pass3<<<dim3(DINNER / 256, TCH, BATCH), 256>>>(A_log, Dv, conv_w, conv_b);

    // 4) out_proj (HMMA fp16)
    hgemm<1, 1024, 2048><<<dim3(1024 / 128, MTOT / 128), 256, GSMEM>>>(b_out, out);
}